// round 3
// baseline (speedup 1.0000x reference)
#include <cuda_runtime.h>
#include <cstdint>

// ---------------------------------------------------------------------------
// Sparse (occupancy-masked) 3D U-Net, grid 96^3, NF=16.
// R2: sorted deterministic compaction, active-tap skipping (exact: skipped
// contributions are exactly 0), persistent conv kernels, padded smem weights.
// ---------------------------------------------------------------------------

#define G0 96
#define G1 48
#define G2 24
#define NV0 (G0*G0*G0)   // 884736
#define NV1 (G1*G1*G1)   // 110592
#define NV2 (G2*G2*G2)   // 13824
#define CB0 (NV0/256)    // 3456 count blocks
#define CB1 (NV1/256)    // 432
#define CB2 (NV2/256)    // 54
#define PGRID 592        // persistent grid (148 SM * 4)

// Scratch (zero-initialized at module load; only active voxels written)
__device__ float g_XM [NV0];
__device__ float g_S0 [16*NV0];
__device__ float g_S1 [16*NV0];
__device__ float g_S2 [32*NV0];
__device__ float g_L1a[32*NV1];
__device__ float g_L1b[32*NV1];
__device__ float g_L1c[32*NV1];
__device__ float g_L1d[64*NV1];
__device__ float g_L2a[64*NV2];
__device__ float g_L2b[64*NV2];
__device__ float g_L2c[64*NV2];
__device__ float g_M1 [NV1];
__device__ float g_M2 [NV2];
__device__ int   g_LIST0[NV0];
__device__ int   g_LIST1[NV1];
__device__ int   g_LIST2[NV2];
__device__ int   g_CNT[4];
__device__ int   g_BCNT[CB0];
__device__ int   g_BOFF[CB0];

// ---------------------------------------------------------------------------
__global__ void k_mask_input(const float* __restrict__ x,
                             const float* __restrict__ occ,
                             float* __restrict__ xm, int n)
{
    int v = blockIdx.x * blockDim.x + threadIdx.x;
    if (v < n) xm[v] = x[v] * occ[v];
}

__global__ void k_maxpool(const float* __restrict__ in,
                          float* __restrict__ out, int gout)
{
    int v = blockIdx.x * blockDim.x + threadIdx.x;
    int n = gout * gout * gout;
    if (v >= n) return;
    int gin = gout * 2;
    int z = v / (gout * gout);
    int y = (v / gout) % gout;
    int x = v % gout;
    float mx = 0.f;
    #pragma unroll
    for (int a = 0; a < 2; a++)
        #pragma unroll
        for (int b = 0; b < 2; b++)
            #pragma unroll
            for (int c = 0; c < 2; c++)
                mx = fmaxf(mx, in[((size_t)(2*z+a)*gin + (2*y+b))*gin + (2*x+c)]);
    out[v] = mx;
}

// --- deterministic sorted compaction: count -> scan -> emit ---------------
__global__ void k_count(const float* __restrict__ m, int n, int* __restrict__ bcnt)
{
    int v = blockIdx.x * 256 + threadIdx.x;
    bool a = (v < n) && (m[v] != 0.f);
    unsigned bal = __ballot_sync(0xffffffffu, a);
    __shared__ int wc[8];
    if ((threadIdx.x & 31) == 0) wc[threadIdx.x >> 5] = __popc(bal);
    __syncthreads();
    if (threadIdx.x == 0) {
        int s = 0;
        #pragma unroll
        for (int i = 0; i < 8; i++) s += wc[i];
        bcnt[blockIdx.x] = s;
    }
}

__global__ void k_scan(const int* __restrict__ bcnt, int nb,
                       int* __restrict__ boff, int* __restrict__ total)
{
    __shared__ int sh[1024];
    __shared__ int carry;
    if (threadIdx.x == 0) carry = 0;
    __syncthreads();
    for (int base = 0; base < nb; base += 1024) {
        int i = base + threadIdx.x;
        int v = (i < nb) ? bcnt[i] : 0;
        sh[threadIdx.x] = v;
        __syncthreads();
        for (int d = 1; d < 1024; d <<= 1) {
            int t = (threadIdx.x >= d) ? sh[threadIdx.x - d] : 0;
            __syncthreads();
            sh[threadIdx.x] += t;
            __syncthreads();
        }
        if (i < nb) boff[i] = carry + sh[threadIdx.x] - v;   // exclusive
        __syncthreads();
        if (threadIdx.x == 0) carry += sh[1023];
        __syncthreads();
    }
    if (threadIdx.x == 0) *total = carry;
}

__global__ void k_emit(const float* __restrict__ m, int n,
                       const int* __restrict__ boff, int* __restrict__ list)
{
    int v = blockIdx.x * 256 + threadIdx.x;
    bool a = (v < n) && (m[v] != 0.f);
    unsigned bal = __ballot_sync(0xffffffffu, a);
    __shared__ int wc[8];
    if ((threadIdx.x & 31) == 0) wc[threadIdx.x >> 5] = __popc(bal);
    __syncthreads();
    int wid = threadIdx.x >> 5;
    int off = boff[blockIdx.x];
    for (int i = 0; i < wid; i++) off += wc[i];
    off += __popc(bal & ((1u << (threadIdx.x & 31)) - 1u));
    if (a) list[off] = v;
}

// ---------------------------------------------------------------------------
// Persistent sparse 3x3x3 SAME conv with active-tap skipping.
// mask[v]==0 => all channels of that voxel are exactly 0 => tap contributes 0.
// Weights staged in smem as [cil][tap][co] padded (+1) for conflict-free LDS
// under divergent tap indices.
// ---------------------------------------------------------------------------
template<int CIN1, int CIN2, int COB, bool RELU, int CHUNK>
__launch_bounds__(128)
__global__ void conv3p(const float* __restrict__ in1, const float* __restrict__ in2,
                       const float* __restrict__ wgl, const float* __restrict__ mask,
                       const int* __restrict__ list, const int* __restrict__ cntp,
                       float* __restrict__ out, int g, int nv)
{
    constexpr int CIN  = CIN1 + CIN2;
    constexpr int WPAD = COB + 1;
    __shared__ float wsh[CHUNK * 27 * WPAD];

    const int cnt    = *cntp;
    const int ntiles = (cnt + 127) >> 7;
    const int co0    = blockIdx.y * COB;
    const int gg     = g * g;

    // Hoist weights entirely when a single chunk covers CIN.
    if (CHUNK >= CIN) {
        for (int i = threadIdx.x; i < CIN * 27 * COB; i += 128) {
            int cil = i / (27 * COB);
            int rem = i - cil * (27 * COB);
            int tap = rem / COB;
            int co  = rem - tap * COB;
            wsh[(cil * 27 + tap) * WPAD + co] =
                wgl[((size_t)(co0 + co) * CIN + cil) * 27 + tap];
        }
        __syncthreads();
    }

    for (int tile = blockIdx.x; tile < ntiles; tile += gridDim.x) {
        const int t   = tile * 128 + threadIdx.x;
        const bool act = t < cnt;
        const int v = act ? list[t] : 0;
        const int z = v / gg;
        const int y = (v / g) % g;
        const int x = v % g;

        // Build packed active-tap list: (tap<<24)|offset.
        int pk[27];
        int na = 0;
        if (act) {
            #pragma unroll
            for (int dz = -1; dz <= 1; dz++) {
                int zz = z + dz;
                if ((unsigned)zz >= (unsigned)g) continue;
                #pragma unroll
                for (int dy = -1; dy <= 1; dy++) {
                    int yy = y + dy;
                    if ((unsigned)yy >= (unsigned)g) continue;
                    int rowo = (zz * g + yy) * g;
                    #pragma unroll
                    for (int dx = -1; dx <= 1; dx++) {
                        int xx = x + dx;
                        if ((unsigned)xx >= (unsigned)g) continue;
                        int o = rowo + xx;
                        if (__ldg(mask + o) != 0.f) {
                            int tap = (dz + 1) * 9 + (dy + 1) * 3 + (dx + 1);
                            pk[na++] = (tap << 24) | o;
                        }
                    }
                }
            }
        }

        float acc[COB];
        #pragma unroll
        for (int co = 0; co < COB; co++) acc[co] = 0.f;

        for (int ci0 = 0; ci0 < CIN; ci0 += CHUNK) {
            if (CHUNK < CIN) {
                __syncthreads();
                for (int i = threadIdx.x; i < CHUNK * 27 * COB; i += 128) {
                    int cil = i / (27 * COB);
                    int rem = i - cil * (27 * COB);
                    int tap = rem / COB;
                    int co  = rem - tap * COB;
                    int ci  = ci0 + cil;
                    wsh[(cil * 27 + tap) * WPAD + co] =
                        (ci < CIN) ? wgl[((size_t)(co0 + co) * CIN + ci) * 27 + tap] : 0.f;
                }
                __syncthreads();
            }
            const int cmax = (CHUNK < CIN - ci0) ? CHUNK : (CIN - ci0);
            for (int cil = 0; cil < cmax; cil++) {
                int ci = ci0 + cil;
                const float* src = (ci < CIN1) ? (in1 + (size_t)ci * nv)
                                               : (in2 + (size_t)(ci - CIN1) * nv);
                for (int k = 0; k < na; k++) {
                    int p = pk[k];
                    float val = __ldg(src + (p & 0xFFFFFF));
                    const float* wp = &wsh[(cil * 27 + (p >> 24)) * WPAD];
                    #pragma unroll
                    for (int co = 0; co < COB; co++)
                        acc[co] += val * wp[co];
                }
            }
        }

        if (act) {
            #pragma unroll
            for (int co = 0; co < COB; co++) {
                float r = acc[co];
                if (RELU) r = fmaxf(r, 0.f);
                out[(size_t)(co0 + co) * nv + v] = r;
            }
        }
    }
}

// ---------------------------------------------------------------------------
// Persistent stride-2 k=2 VALID downsample conv with fine-mask tap skipping.
// ---------------------------------------------------------------------------
template<int CIN, int COB>
__launch_bounds__(128)
__global__ void down2p(const float* __restrict__ in, const float* __restrict__ wgl,
                       const float* __restrict__ maskf,
                       const int* __restrict__ list, const int* __restrict__ cntp,
                       float* __restrict__ out, int gout, int nvin, int nvout)
{
    constexpr int WPAD = COB + 1;
    __shared__ float wsh[CIN * 8 * WPAD];
    const int cnt    = *cntp;
    const int ntiles = (cnt + 127) >> 7;
    const int co0    = blockIdx.y * COB;
    const int gin    = gout * 2;

    for (int i = threadIdx.x; i < CIN * 8 * COB; i += 128) {
        int ci  = i / (8 * COB);
        int rem = i - ci * (8 * COB);
        int tap = rem / COB;
        int co  = rem - tap * COB;
        wsh[(ci * 8 + tap) * WPAD + co] = wgl[((size_t)(co0 + co) * CIN + ci) * 8 + tap];
    }
    __syncthreads();

    for (int tile = blockIdx.x; tile < ntiles; tile += gridDim.x) {
        const int t   = tile * 128 + threadIdx.x;
        const bool act = t < cnt;
        const int v = act ? list[t] : 0;
        const int z = v / (gout * gout);
        const int y = (v / gout) % gout;
        const int x = v % gout;

        int pk[8];
        int na = 0;
        if (act) {
            #pragma unroll
            for (int kd = 0; kd < 2; kd++)
                #pragma unroll
                for (int kh = 0; kh < 2; kh++)
                    #pragma unroll
                    for (int kw = 0; kw < 2; kw++) {
                        int o = ((2*z + kd) * gin + (2*y + kh)) * gin + (2*x + kw);
                        if (__ldg(maskf + o) != 0.f)
                            pk[na++] = ((kd*4 + kh*2 + kw) << 24) | o;
                    }
        }

        float acc[COB];
        #pragma unroll
        for (int co = 0; co < COB; co++) acc[co] = 0.f;

        for (int ci = 0; ci < CIN; ci++) {
            const float* src = in + (size_t)ci * nvin;
            for (int k = 0; k < na; k++) {
                int p = pk[k];
                float val = __ldg(src + (p & 0xFFFFFF));
                const float* wp = &wsh[(ci * 8 + (p >> 24)) * WPAD];
                #pragma unroll
                for (int co = 0; co < COB; co++)
                    acc[co] += val * wp[co];
            }
        }

        if (act) {
            #pragma unroll
            for (int co = 0; co < COB; co++)
                out[(size_t)(co0 + co) * nvout + v] = acc[co];
        }
    }
}

// ---------------------------------------------------------------------------
// Persistent k=2 s=2 transpose conv (upsample). Parent coarse voxel of an
// active fine voxel is always active (maxpool), so no skipping needed.
//   y[o, 2m+a, ...] = sum_i x[i,m,...] * w[o,i,1-a,1-b,1-c]
// ---------------------------------------------------------------------------
template<int CIN, int COB>
__launch_bounds__(128)
__global__ void up2p(const float* __restrict__ in, const float* __restrict__ wgl,
                     const int* __restrict__ list, const int* __restrict__ cntp,
                     float* __restrict__ out, int gout, int nvin, int nvout)
{
    constexpr int WPAD = COB + 1;
    __shared__ float wsh[CIN * 8 * WPAD];
    const int cnt    = *cntp;
    const int ntiles = (cnt + 127) >> 7;
    const int co0    = blockIdx.y * COB;
    const int gin    = gout >> 1;

    for (int i = threadIdx.x; i < CIN * 8 * COB; i += 128) {
        int ci  = i / (8 * COB);
        int rem = i - ci * (8 * COB);
        int tap = rem / COB;
        int co  = rem - tap * COB;
        wsh[(ci * 8 + tap) * WPAD + co] = wgl[((size_t)(co0 + co) * CIN + ci) * 8 + tap];
    }
    __syncthreads();

    for (int tile = blockIdx.x; tile < ntiles; tile += gridDim.x) {
        const int t   = tile * 128 + threadIdx.x;
        const bool act = t < cnt;
        const int v = act ? list[t] : 0;
        const int z = v / (gout * gout);
        const int y = (v / gout) % gout;
        const int x = v % gout;
        const int p   = ((z >> 1) * gin + (y >> 1)) * gin + (x >> 1);
        const int tap = (1 - (z & 1)) * 4 + (1 - (y & 1)) * 2 + (1 - (x & 1));

        float acc[COB];
        #pragma unroll
        for (int co = 0; co < COB; co++) acc[co] = 0.f;

        if (act) {
            #pragma unroll 4
            for (int ci = 0; ci < CIN; ci++) {
                float val = __ldg(in + (size_t)ci * nvin + p);
                const float* wp = &wsh[(ci * 8 + tap) * WPAD];
                #pragma unroll
                for (int co = 0; co < COB; co++)
                    acc[co] += val * wp[co];
            }
            #pragma unroll
            for (int co = 0; co < COB; co++)
                out[(size_t)(co0 + co) * nvout + v] = acc[co];
        }
    }
}

// ---------------------------------------------------------------------------
extern "C" void kernel_launch(void* const* d_in, const int* in_sizes, int n_in,
                              void* d_out, int out_size)
{
    const float* x      = (const float*)d_in[0];
    const float* occ    = (const float*)d_in[1];
    const float* w_in   = (const float*)d_in[2];
    const float* w_e0d  = (const float*)d_in[3];
    const float* w_e0a  = (const float*)d_in[4];
    const float* w_e0b  = (const float*)d_in[5];
    const float* w_e1d  = (const float*)d_in[6];
    const float* w_e1a  = (const float*)d_in[7];
    const float* w_e1b  = (const float*)d_in[8];
    const float* w_d0u  = (const float*)d_in[9];
    const float* w_d0a  = (const float*)d_in[10];
    const float* w_d0b  = (const float*)d_in[11];
    const float* w_d1u  = (const float*)d_in[12];
    const float* w_d1a  = (const float*)d_in[13];
    const float* w_d1b  = (const float*)d_in[14];
    const float* w_oa   = (const float*)d_in[15];
    const float* w_ob   = (const float*)d_in[16];

    float *XM, *S0, *S1, *S2, *L1a, *L1b, *L1c, *L1d, *L2a, *L2b, *L2c, *M1, *M2;
    int *LIST0, *LIST1, *LIST2, *CNT, *BCNT, *BOFF;
    cudaGetSymbolAddress((void**)&XM,  g_XM);
    cudaGetSymbolAddress((void**)&S0,  g_S0);
    cudaGetSymbolAddress((void**)&S1,  g_S1);
    cudaGetSymbolAddress((void**)&S2,  g_S2);
    cudaGetSymbolAddress((void**)&L1a, g_L1a);
    cudaGetSymbolAddress((void**)&L1b, g_L1b);
    cudaGetSymbolAddress((void**)&L1c, g_L1c);
    cudaGetSymbolAddress((void**)&L1d, g_L1d);
    cudaGetSymbolAddress((void**)&L2a, g_L2a);
    cudaGetSymbolAddress((void**)&L2b, g_L2b);
    cudaGetSymbolAddress((void**)&L2c, g_L2c);
    cudaGetSymbolAddress((void**)&M1,  g_M1);
    cudaGetSymbolAddress((void**)&M2,  g_M2);
    cudaGetSymbolAddress((void**)&LIST0, g_LIST0);
    cudaGetSymbolAddress((void**)&LIST1, g_LIST1);
    cudaGetSymbolAddress((void**)&LIST2, g_LIST2);
    cudaGetSymbolAddress((void**)&CNT,   g_CNT);
    cudaGetSymbolAddress((void**)&BCNT,  g_BCNT);
    cudaGetSymbolAddress((void**)&BOFF,  g_BOFF);

    float* OUT = (float*)d_out;

    // Masks
    k_mask_input<<<NV0/128, 128>>>(x, occ, XM, NV0);
    k_maxpool<<<NV1/128, 128>>>(occ, M1, G1);
    k_maxpool<<<NV2/128, 128>>>(M1, M2, G2);

    // Sorted deterministic compaction per level
    k_count<<<CB0, 256>>>(occ, NV0, BCNT);
    k_scan <<<1, 1024>>>(BCNT, CB0, BOFF, CNT + 0);
    k_emit <<<CB0, 256>>>(occ, NV0, BOFF, LIST0);

    k_count<<<CB1, 256>>>(M1, NV1, BCNT);
    k_scan <<<1, 1024>>>(BCNT, CB1, BOFF, CNT + 1);
    k_emit <<<CB1, 256>>>(M1, NV1, BOFF, LIST1);

    k_count<<<CB2, 256>>>(M2, NV2, BCNT);
    k_scan <<<1, 1024>>>(BCNT, CB2, BOFF, CNT + 2);
    k_emit <<<CB2, 256>>>(M2, NV2, BOFF, LIST2);

    // input block: conv3 1->16 @96^3
    conv3p<1, 0, 16, false, 1><<<dim3(PGRID, 1), 128>>>(XM, (const float*)nullptr, w_in, occ, LIST0, CNT + 0, S0, G0, NV0);

    // encoder level 0
    down2p<16, 32><<<dim3(PGRID, 1), 128>>>(S0, w_e0d, occ, LIST1, CNT + 1, L1a, G1, NV0, NV1);
    conv3p<32, 0, 32, true,  8><<<dim3(PGRID, 1), 128>>>(L1a, (const float*)nullptr, w_e0a, M1, LIST1, CNT + 1, L1b, G1, NV1);
    conv3p<32, 0, 32, false, 8><<<dim3(PGRID, 1), 128>>>(L1b, (const float*)nullptr, w_e0b, M1, LIST1, CNT + 1, L1c, G1, NV1); // skip1

    // encoder level 1
    down2p<32, 32><<<dim3(108, 2), 128>>>(L1c, w_e1d, M1, LIST2, CNT + 2, L2a, G2, NV1, NV2);
    conv3p<64, 0, 32, true,  8><<<dim3(108, 2), 128>>>(L2a, (const float*)nullptr, w_e1a, M2, LIST2, CNT + 2, L2b, G2, NV2);
    conv3p<64, 0, 32, false, 8><<<dim3(108, 2), 128>>>(L2b, (const float*)nullptr, w_e1b, M2, LIST2, CNT + 2, L2c, G2, NV2);

    // decoder stage 0 (back to level 1)
    up2p<64, 16><<<dim3(PGRID, 2), 128>>>(L2c, w_d0u, LIST1, CNT + 1, L1a, G1, NV2, NV1);
    conv3p<32, 32, 32, true, 8><<<dim3(PGRID, 2), 128>>>(L1a, L1c, w_d0a, M1, LIST1, CNT + 1, L1d, G1, NV1); // concat 64->64
    conv3p<64, 0, 32, false, 8><<<dim3(PGRID, 1), 128>>>(L1d, (const float*)nullptr, w_d0b, M1, LIST1, CNT + 1, L1b, G1, NV1); // 64->32

    // decoder stage 1 (back to level 0)
    up2p<32, 16><<<dim3(PGRID, 1), 128>>>(L1b, w_d1u, LIST0, CNT + 0, S1, G0, NV1, NV0);
    conv3p<16, 16, 32, true, 8><<<dim3(PGRID, 1), 128>>>(S1, S0, w_d1a, occ, LIST0, CNT + 0, S2, G0, NV0); // concat 32->32
    conv3p<32, 0, 16, false, 8><<<dim3(PGRID, 1), 128>>>(S2, (const float*)nullptr, w_d1b, occ, LIST0, CNT + 0, S1, G0, NV0); // 32->16

    // output block
    conv3p<16, 0, 16, true, 16><<<dim3(PGRID, 1), 128>>>(S1, (const float*)nullptr, w_oa, occ, LIST0, CNT + 0, S0, G0, NV0);
    cudaMemsetAsync(d_out, 0, (size_t)out_size * sizeof(float));
    conv3p<16, 0, 5, false, 16><<<dim3(PGRID, 1), 128>>>(S0, (const float*)nullptr, w_ob, occ, LIST0, CNT + 0, OUT, G0, NV0);
}

// round 4
// speedup vs baseline: 1.4628x; 1.4628x over previous
#include <cuda_runtime.h>
#include <cstdint>

// ---------------------------------------------------------------------------
// Sparse (occupancy-masked) 3D U-Net, 96^3, NF=16.
// R3: channel-major activations, precomputed global tap lists, na-sorted
// voxel lists, one-tile-per-block convs, float4 loads/stores.
// ---------------------------------------------------------------------------

#define G0 96
#define G1 48
#define G2 24
#define NV0 (G0*G0*G0)   // 884736
#define NV1 (G1*G1*G1)   // 110592
#define NV2 (G2*G2*G2)   // 13824
#define CB0 (NV0/256)
#define CB1 (NV1/256)
#define CB2 (NV2/256)
#define NB0 ((NV0+127)/128)
#define NB1 ((NV1+127)/128)
#define NB2 ((NV2+127)/128)

// Activations, channel-major [voxel][channel]
__device__ float g_XM  [NV0];
__device__ float g_CAT0[(size_t)32*NV0];  // ch0-15 d1u out, ch16-31 conv_in out (skip0)
__device__ float g_A32 [(size_t)32*NV0];  // d1a out
__device__ float g_A16a[(size_t)16*NV0];  // d1b out
__device__ float g_A16b[(size_t)16*NV0];  // out_a out
__device__ float g_B32a[(size_t)32*NV1];  // e0d out; reused as d0b out
__device__ float g_B32b[(size_t)32*NV1];  // e0a out
__device__ float g_CAT1[(size_t)64*NV1];  // ch0-31 d0u out, ch32-63 e0b out (skip1)
__device__ float g_B64 [(size_t)64*NV1];  // d0a out
__device__ float g_C64a[(size_t)64*NV2];
__device__ float g_C64b[(size_t)64*NV2];
__device__ float g_C64c[(size_t)64*NV2];
__device__ float g_M1[NV1];
__device__ float g_M2[NV2];

__device__ int g_LISTU[NV0];
__device__ int g_NAU  [NV0];
__device__ int g_LIST0[NV0], g_LIST1[NV1], g_LIST2[NV2];
__device__ int g_NA0[NV0], g_NA1[NV1], g_NA2[NV2];
__device__ int g_TAP0[(size_t)27*NV0];
__device__ int g_TAP1[(size_t)27*NV1];
__device__ int g_TAP2[(size_t)27*NV2];
__device__ int g_CNT[4];
__device__ int g_BCNT[CB0], g_BOFF[CB0];
__device__ int g_HIST[32], g_HOFF[32];

// ---------------------------------------------------------------------------
__global__ void k_mask_input(const float* __restrict__ x,
                             const float* __restrict__ occ,
                             float* __restrict__ xm, int n)
{
    int v = blockIdx.x * blockDim.x + threadIdx.x;
    if (v < n) xm[v] = x[v] * occ[v];
}

__global__ void k_maxpool(const float* __restrict__ in,
                          float* __restrict__ out, int gout)
{
    int v = blockIdx.x * blockDim.x + threadIdx.x;
    int n = gout * gout * gout;
    if (v >= n) return;
    int gin = gout * 2;
    int z = v / (gout * gout), y = (v / gout) % gout, x = v % gout;
    float mx = 0.f;
    #pragma unroll
    for (int a = 0; a < 2; a++)
        #pragma unroll
        for (int b = 0; b < 2; b++)
            #pragma unroll
            for (int c = 0; c < 2; c++)
                mx = fmaxf(mx, in[((size_t)(2*z+a)*gin + (2*y+b))*gin + (2*x+c)]);
    out[v] = mx;
}

// --- deterministic compaction: count -> scan -> emit ----------------------
__global__ void k_count(const float* __restrict__ m, int n, int* __restrict__ bcnt)
{
    int v = blockIdx.x * 256 + threadIdx.x;
    bool a = (v < n) && (m[v] != 0.f);
    unsigned bal = __ballot_sync(0xffffffffu, a);
    __shared__ int wc[8];
    if ((threadIdx.x & 31) == 0) wc[threadIdx.x >> 5] = __popc(bal);
    __syncthreads();
    if (threadIdx.x == 0) {
        int s = 0;
        #pragma unroll
        for (int i = 0; i < 8; i++) s += wc[i];
        bcnt[blockIdx.x] = s;
    }
}

__global__ void k_scan(const int* __restrict__ bcnt, int nb,
                       int* __restrict__ boff, int* __restrict__ total)
{
    __shared__ int sh[1024];
    __shared__ int carry;
    if (threadIdx.x == 0) carry = 0;
    __syncthreads();
    for (int base = 0; base < nb; base += 1024) {
        int i = base + threadIdx.x;
        int v = (i < nb) ? bcnt[i] : 0;
        sh[threadIdx.x] = v;
        __syncthreads();
        for (int d = 1; d < 1024; d <<= 1) {
            int t = (threadIdx.x >= d) ? sh[threadIdx.x - d] : 0;
            __syncthreads();
            sh[threadIdx.x] += t;
            __syncthreads();
        }
        if (i < nb) boff[i] = carry + sh[threadIdx.x] - v;
        __syncthreads();
        if (threadIdx.x == 0) carry += sh[1023];
        __syncthreads();
    }
    if (threadIdx.x == 0) *total = carry;
}

__global__ void k_emit(const float* __restrict__ m, int n,
                       const int* __restrict__ boff, int* __restrict__ list)
{
    int v = blockIdx.x * 256 + threadIdx.x;
    bool a = (v < n) && (m[v] != 0.f);
    unsigned bal = __ballot_sync(0xffffffffu, a);
    __shared__ int wc[8];
    if ((threadIdx.x & 31) == 0) wc[threadIdx.x >> 5] = __popc(bal);
    __syncthreads();
    int wid = threadIdx.x >> 5;
    int off = boff[blockIdx.x];
    for (int i = 0; i < wid; i++) off += wc[i];
    off += __popc(bal & ((1u << (threadIdx.x & 31)) - 1u));
    if (a) list[off] = v;
}

// --- na computation, histogram, counting-sort by na, tap lists ------------
__global__ void k_zero32(int* a) { if (threadIdx.x < 32) a[threadIdx.x] = 0; }

__global__ void k_na(const float* __restrict__ m, const int* __restrict__ list,
                     const int* __restrict__ cntp, int g,
                     int* __restrict__ nau, int* __restrict__ hist)
{
    int cnt = *cntp;
    int t = blockIdx.x * 128 + threadIdx.x;
    if (t >= cnt) return;
    int v = list[t];
    int gg = g * g;
    int z = v / gg, y = (v / g) % g, x = v % g;
    int na = 0;
    #pragma unroll
    for (int dz = -1; dz <= 1; dz++) {
        int zz = z + dz; if ((unsigned)zz >= (unsigned)g) continue;
        #pragma unroll
        for (int dy = -1; dy <= 1; dy++) {
            int yy = y + dy; if ((unsigned)yy >= (unsigned)g) continue;
            int ro = (zz * g + yy) * g;
            #pragma unroll
            for (int dx = -1; dx <= 1; dx++) {
                int xx = x + dx; if ((unsigned)xx >= (unsigned)g) continue;
                if (__ldg(m + ro + xx) != 0.f) na++;
            }
        }
    }
    nau[t] = na;
    atomicAdd(&hist[na], 1);
}

__global__ void k_scan28(const int* __restrict__ hist, int* __restrict__ hoff)
{
    if (threadIdx.x == 0) {
        int s = 0;
        for (int i = 0; i < 32; i++) { hoff[i] = s; s += hist[i]; }
    }
}

__global__ void k_sortscatter(const int* __restrict__ listu, const int* __restrict__ nau,
                              const int* __restrict__ cntp,
                              int* __restrict__ hoff, int* __restrict__ list)
{
    int cnt = *cntp;
    int t = blockIdx.x * 128 + threadIdx.x;
    if (t >= cnt) return;
    int p = atomicAdd(&hoff[nau[t]], 1);
    list[p] = listu[t];
}

__global__ void k_taps(const float* __restrict__ m, const int* __restrict__ list,
                       const int* __restrict__ cntp, int g, int cap,
                       int* __restrict__ TAP, int* __restrict__ NA)
{
    int cnt = *cntp;
    int t = blockIdx.x * 128 + threadIdx.x;
    if (t >= cnt) return;
    int v = list[t];
    int gg = g * g;
    int z = v / gg, y = (v / g) % g, x = v % g;
    int na = 0;
    #pragma unroll
    for (int dz = -1; dz <= 1; dz++) {
        int zz = z + dz; if ((unsigned)zz >= (unsigned)g) continue;
        #pragma unroll
        for (int dy = -1; dy <= 1; dy++) {
            int yy = y + dy; if ((unsigned)yy >= (unsigned)g) continue;
            int ro = (zz * g + yy) * g;
            #pragma unroll
            for (int dx = -1; dx <= 1; dx++) {
                int xx = x + dx; if ((unsigned)xx >= (unsigned)g) continue;
                int o = ro + xx;
                if (__ldg(m + o) != 0.f) {
                    int tap = (dz + 1) * 9 + (dy + 1) * 3 + (dx + 1);
                    TAP[(size_t)na * cap + t] = (tap << 24) | o;
                    na++;
                }
            }
        }
    }
    NA[t] = na;
}

// ---------------------------------------------------------------------------
// Sparse 3x3x3 conv, channel-major in/out, precomputed tap lists.
// ---------------------------------------------------------------------------
template<int CIN, int COB, bool RELU, int CHUNK, bool OUTP>
__launch_bounds__(128)
__global__ void conv3cm(const float* __restrict__ in, int istr,
                        const float* __restrict__ wgl,
                        const int* __restrict__ TAP, const int* __restrict__ NAs,
                        const int* __restrict__ list, const int* __restrict__ cntp,
                        float* __restrict__ out, int ostr, int cap)
{
    constexpr int WPAD = COB + 1;
    __shared__ float wsh[CHUNK * 27 * WPAD];
    const int cnt = *cntp;
    if (blockIdx.x * 128 >= cnt) return;
    const int co0 = blockIdx.y * COB;
    const int t   = blockIdx.x * 128 + threadIdx.x;
    const bool act = t < cnt;
    const int v  = act ? list[t] : 0;
    const int na = act ? NAs[t] : 0;

    float acc[COB];
    #pragma unroll
    for (int co = 0; co < COB; co++) acc[co] = 0.f;

    for (int ci0 = 0; ci0 < CIN; ci0 += CHUNK) {
        __syncthreads();
        for (int i = threadIdx.x; i < CHUNK * 27 * COB; i += 128) {
            int cil = i / (27 * COB);
            int rem = i - cil * (27 * COB);
            int tap = rem / COB;
            int co  = rem - tap * COB;
            wsh[(cil * 27 + tap) * WPAD + co] =
                wgl[((size_t)(co0 + co) * CIN + (ci0 + cil)) * 27 + tap];
        }
        __syncthreads();

        if constexpr (CIN == 1) {
            for (int k = 0; k < na; k++) {
                int p = __ldg(TAP + (size_t)k * cap + t);
                float xs = __ldg(in + (p & 0xFFFFFF));
                const float* wr = &wsh[(p >> 24) * WPAD];
                #pragma unroll
                for (int co = 0; co < COB; co++) acc[co] += xs * wr[co];
            }
        } else {
            for (int k = 0; k < na; k++) {
                int p = __ldg(TAP + (size_t)k * cap + t);
                int off = p & 0xFFFFFF;
                int tap = p >> 24;
                const float* xin = in + (size_t)off * istr + ci0;
                #pragma unroll
                for (int cq = 0; cq < CHUNK / 4; cq++) {
                    float4 xv = *reinterpret_cast<const float4*>(xin + cq * 4);
                    #pragma unroll
                    for (int j = 0; j < 4; j++) {
                        float xs = (j == 0) ? xv.x : (j == 1) ? xv.y : (j == 2) ? xv.z : xv.w;
                        const float* wr = &wsh[((cq * 4 + j) * 27 + tap) * WPAD];
                        #pragma unroll
                        for (int co = 0; co < COB; co++) acc[co] += xs * wr[co];
                    }
                }
            }
        }
    }

    if (act) {
        if constexpr (OUTP) {
            #pragma unroll
            for (int co = 0; co < COB; co++) {
                float r = acc[co];
                if (RELU) r = fmaxf(r, 0.f);
                out[(size_t)(co0 + co) * ostr + v] = r;
            }
        } else {
            float* op = out + (size_t)v * ostr + co0;
            #pragma unroll
            for (int co = 0; co < COB; co += 4) {
                float4 r = make_float4(acc[co], acc[co+1], acc[co+2], acc[co+3]);
                if (RELU) { r.x = fmaxf(r.x, 0.f); r.y = fmaxf(r.y, 0.f);
                            r.z = fmaxf(r.z, 0.f); r.w = fmaxf(r.w, 0.f); }
                *reinterpret_cast<float4*>(op + co) = r;
            }
        }
    }
}

// ---------------------------------------------------------------------------
// Stride-2 k=2 downsample, channel-major, fine-mask tap skipping.
// ---------------------------------------------------------------------------
template<int CIN, int COB>
__launch_bounds__(128)
__global__ void down2cm(const float* __restrict__ in, int istr,
                        const float* __restrict__ wgl,
                        const float* __restrict__ maskf,
                        const int* __restrict__ list, const int* __restrict__ cntp,
                        float* __restrict__ out, int ostr, int gout)
{
    constexpr int WPAD = COB + 1;
    __shared__ float wsh[CIN * 8 * WPAD];
    const int cnt = *cntp;
    if (blockIdx.x * 128 >= cnt) return;
    const int co0 = blockIdx.y * COB;
    for (int i = threadIdx.x; i < CIN * 8 * COB; i += 128) {
        int ci  = i / (8 * COB);
        int rem = i - ci * (8 * COB);
        int tap = rem / COB;
        int co  = rem - tap * COB;
        wsh[(ci * 8 + tap) * WPAD + co] = wgl[((size_t)(co0 + co) * CIN + ci) * 8 + tap];
    }
    __syncthreads();

    const int t = blockIdx.x * 128 + threadIdx.x;
    const bool act = t < cnt;
    const int v = act ? list[t] : 0;
    const int z = v / (gout * gout), y = (v / gout) % gout, x = v % gout;
    const int gin = gout * 2;

    float acc[COB];
    #pragma unroll
    for (int co = 0; co < COB; co++) acc[co] = 0.f;

    #pragma unroll
    for (int tap = 0; tap < 8; tap++) {
        int kd = tap >> 2, kh = (tap >> 1) & 1, kw = tap & 1;
        int off = ((2*z + kd) * gin + (2*y + kh)) * gin + (2*x + kw);
        if (act && __ldg(maskf + off) != 0.f) {
            const float* xin = in + (size_t)off * istr;
            #pragma unroll
            for (int cq = 0; cq < CIN / 4; cq++) {
                float4 xv = *reinterpret_cast<const float4*>(xin + cq * 4);
                #pragma unroll
                for (int j = 0; j < 4; j++) {
                    float xs = (j == 0) ? xv.x : (j == 1) ? xv.y : (j == 2) ? xv.z : xv.w;
                    const float* wr = &wsh[((cq * 4 + j) * 8 + tap) * WPAD];
                    #pragma unroll
                    for (int co = 0; co < COB; co++) acc[co] += xs * wr[co];
                }
            }
        }
    }

    if (act) {
        float* op = out + (size_t)v * ostr + co0;
        #pragma unroll
        for (int co = 0; co < COB; co += 4)
            *reinterpret_cast<float4*>(op + co) =
                make_float4(acc[co], acc[co+1], acc[co+2], acc[co+3]);
    }
}

// ---------------------------------------------------------------------------
// k=2 s=2 transpose conv (upsample), channel-major. Parent always active.
//   y[o,2m+a,..] = sum_i x[i,m,..] * w[o,i,1-a,1-b,1-c]
// ---------------------------------------------------------------------------
template<int CIN, int COB>
__launch_bounds__(128)
__global__ void up2cm(const float* __restrict__ in, int istr,
                      const float* __restrict__ wgl,
                      const int* __restrict__ list, const int* __restrict__ cntp,
                      float* __restrict__ out, int ostr, int gout)
{
    constexpr int WPAD = COB + 1;
    __shared__ float wsh[CIN * 8 * WPAD];
    const int cnt = *cntp;
    if (blockIdx.x * 128 >= cnt) return;
    const int co0 = blockIdx.y * COB;
    for (int i = threadIdx.x; i < CIN * 8 * COB; i += 128) {
        int ci  = i / (8 * COB);
        int rem = i - ci * (8 * COB);
        int tap = rem / COB;
        int co  = rem - tap * COB;
        wsh[(ci * 8 + tap) * WPAD + co] = wgl[((size_t)(co0 + co) * CIN + ci) * 8 + tap];
    }
    __syncthreads();

    const int t = blockIdx.x * 128 + threadIdx.x;
    const bool act = t < cnt;
    const int v = act ? list[t] : 0;
    const int z = v / (gout * gout), y = (v / gout) % gout, x = v % gout;
    const int gin = gout >> 1;
    const int p   = ((z >> 1) * gin + (y >> 1)) * gin + (x >> 1);
    const int tap = (1 - (z & 1)) * 4 + (1 - (y & 1)) * 2 + (1 - (x & 1));

    float acc[COB];
    #pragma unroll
    for (int co = 0; co < COB; co++) acc[co] = 0.f;

    if (act) {
        const float* xin = in + (size_t)p * istr;
        #pragma unroll
        for (int cq = 0; cq < CIN / 4; cq++) {
            float4 xv = *reinterpret_cast<const float4*>(xin + cq * 4);
            #pragma unroll
            for (int j = 0; j < 4; j++) {
                float xs = (j == 0) ? xv.x : (j == 1) ? xv.y : (j == 2) ? xv.z : xv.w;
                const float* wr = &wsh[((cq * 4 + j) * 8 + tap) * WPAD];
                #pragma unroll
                for (int co = 0; co < COB; co++) acc[co] += xs * wr[co];
            }
        }
        float* op = out + (size_t)v * ostr + co0;
        #pragma unroll
        for (int co = 0; co < COB; co += 4)
            *reinterpret_cast<float4*>(op + co) =
                make_float4(acc[co], acc[co+1], acc[co+2], acc[co+3]);
    }
}

// ---------------------------------------------------------------------------
extern "C" void kernel_launch(void* const* d_in, const int* in_sizes, int n_in,
                              void* d_out, int out_size)
{
    const float* x     = (const float*)d_in[0];
    const float* occ   = (const float*)d_in[1];
    const float* w_in  = (const float*)d_in[2];
    const float* w_e0d = (const float*)d_in[3];
    const float* w_e0a = (const float*)d_in[4];
    const float* w_e0b = (const float*)d_in[5];
    const float* w_e1d = (const float*)d_in[6];
    const float* w_e1a = (const float*)d_in[7];
    const float* w_e1b = (const float*)d_in[8];
    const float* w_d0u = (const float*)d_in[9];
    const float* w_d0a = (const float*)d_in[10];
    const float* w_d0b = (const float*)d_in[11];
    const float* w_d1u = (const float*)d_in[12];
    const float* w_d1a = (const float*)d_in[13];
    const float* w_d1b = (const float*)d_in[14];
    const float* w_oa  = (const float*)d_in[15];
    const float* w_ob  = (const float*)d_in[16];

    float *XM, *CAT0, *A32, *A16a, *A16b, *B32a, *B32b, *CAT1, *B64;
    float *C64a, *C64b, *C64c, *M1, *M2;
    int *LISTU, *NAU, *LIST0, *LIST1, *LIST2, *NA0, *NA1, *NA2;
    int *TAP0, *TAP1, *TAP2, *CNT, *BCNT, *BOFF, *HIST, *HOFF;
    cudaGetSymbolAddress((void**)&XM,   g_XM);
    cudaGetSymbolAddress((void**)&CAT0, g_CAT0);
    cudaGetSymbolAddress((void**)&A32,  g_A32);
    cudaGetSymbolAddress((void**)&A16a, g_A16a);
    cudaGetSymbolAddress((void**)&A16b, g_A16b);
    cudaGetSymbolAddress((void**)&B32a, g_B32a);
    cudaGetSymbolAddress((void**)&B32b, g_B32b);
    cudaGetSymbolAddress((void**)&CAT1, g_CAT1);
    cudaGetSymbolAddress((void**)&B64,  g_B64);
    cudaGetSymbolAddress((void**)&C64a, g_C64a);
    cudaGetSymbolAddress((void**)&C64b, g_C64b);
    cudaGetSymbolAddress((void**)&C64c, g_C64c);
    cudaGetSymbolAddress((void**)&M1,   g_M1);
    cudaGetSymbolAddress((void**)&M2,   g_M2);
    cudaGetSymbolAddress((void**)&LISTU, g_LISTU);
    cudaGetSymbolAddress((void**)&NAU,   g_NAU);
    cudaGetSymbolAddress((void**)&LIST0, g_LIST0);
    cudaGetSymbolAddress((void**)&LIST1, g_LIST1);
    cudaGetSymbolAddress((void**)&LIST2, g_LIST2);
    cudaGetSymbolAddress((void**)&NA0,   g_NA0);
    cudaGetSymbolAddress((void**)&NA1,   g_NA1);
    cudaGetSymbolAddress((void**)&NA2,   g_NA2);
    cudaGetSymbolAddress((void**)&TAP0,  g_TAP0);
    cudaGetSymbolAddress((void**)&TAP1,  g_TAP1);
    cudaGetSymbolAddress((void**)&TAP2,  g_TAP2);
    cudaGetSymbolAddress((void**)&CNT,   g_CNT);
    cudaGetSymbolAddress((void**)&BCNT,  g_BCNT);
    cudaGetSymbolAddress((void**)&BOFF,  g_BOFF);
    cudaGetSymbolAddress((void**)&HIST,  g_HIST);
    cudaGetSymbolAddress((void**)&HOFF,  g_HOFF);

    float* OUT = (float*)d_out;

    // Masks + masked input
    k_mask_input<<<NV0/128, 128>>>(x, occ, XM, NV0);
    k_maxpool<<<NB1, 128>>>(occ, M1, G1);
    k_maxpool<<<NB2, 128>>>(M1, M2, G2);

    // Level 0: compact, sort by na, tap lists
    k_count<<<CB0, 256>>>(occ, NV0, BCNT);
    k_scan <<<1, 1024>>>(BCNT, CB0, BOFF, CNT + 0);
    k_emit <<<CB0, 256>>>(occ, NV0, BOFF, LISTU);
    k_zero32<<<1, 32>>>(HIST);
    k_na<<<NB0, 128>>>(occ, LISTU, CNT + 0, G0, NAU, HIST);
    k_scan28<<<1, 32>>>(HIST, HOFF);
    k_sortscatter<<<NB0, 128>>>(LISTU, NAU, CNT + 0, HOFF, LIST0);
    k_taps<<<NB0, 128>>>(occ, LIST0, CNT + 0, G0, NV0, TAP0, NA0);

    // Level 1
    k_count<<<CB1, 256>>>(M1, NV1, BCNT);
    k_scan <<<1, 1024>>>(BCNT, CB1, BOFF, CNT + 1);
    k_emit <<<CB1, 256>>>(M1, NV1, BOFF, LISTU);
    k_zero32<<<1, 32>>>(HIST);
    k_na<<<NB1, 128>>>(M1, LISTU, CNT + 1, G1, NAU, HIST);
    k_scan28<<<1, 32>>>(HIST, HOFF);
    k_sortscatter<<<NB1, 128>>>(LISTU, NAU, CNT + 1, HOFF, LIST1);
    k_taps<<<NB1, 128>>>(M1, LIST1, CNT + 1, G1, NV1, TAP1, NA1);

    // Level 2
    k_count<<<CB2, 256>>>(M2, NV2, BCNT);
    k_scan <<<1, 1024>>>(BCNT, CB2, BOFF, CNT + 2);
    k_emit <<<CB2, 256>>>(M2, NV2, BOFF, LISTU);
    k_zero32<<<1, 32>>>(HIST);
    k_na<<<NB2, 128>>>(M2, LISTU, CNT + 2, G2, NAU, HIST);
    k_scan28<<<1, 32>>>(HIST, HOFF);
    k_sortscatter<<<NB2, 128>>>(LISTU, NAU, CNT + 2, HOFF, LIST2);
    k_taps<<<NB2, 128>>>(M2, LIST2, CNT + 2, G2, NV2, TAP2, NA2);

    // ---- network ----
    // conv_in: 1 -> 16, write skip0 into CAT0 ch16..31
    conv3cm<1, 16, false, 1, false><<<dim3(NB0, 1), 128>>>(
        XM, 1, w_in, TAP0, NA0, LIST0, CNT + 0, CAT0 + 16, 32, NV0);

    // e0d: 16 -> 32 (down to L1)
    down2cm<16, 32><<<dim3(NB1, 1), 128>>>(
        CAT0 + 16, 32, w_e0d, occ, LIST1, CNT + 1, B32a, 32, G1);
    // e0a: 32 -> 32 relu
    conv3cm<32, 32, true, 8, false><<<dim3(NB1, 1), 128>>>(
        B32a, 32, w_e0a, TAP1, NA1, LIST1, CNT + 1, B32b, 32, NV1);
    // e0b: 32 -> 32, write skip1 into CAT1 ch32..63
    conv3cm<32, 32, false, 8, false><<<dim3(NB1, 1), 128>>>(
        B32b, 32, w_e0b, TAP1, NA1, LIST1, CNT + 1, CAT1 + 32, 64, NV1);

    // e1d: 32 -> 64 (down to L2)
    down2cm<32, 32><<<dim3(NB2, 2), 128>>>(
        CAT1 + 32, 64, w_e1d, M1, LIST2, CNT + 2, C64a, 64, G2);
    // e1a: 64 -> 64 relu
    conv3cm<64, 32, true, 8, false><<<dim3(NB2, 2), 128>>>(
        C64a, 64, w_e1a, TAP2, NA2, LIST2, CNT + 2, C64b, 64, NV2);
    // e1b: 64 -> 64
    conv3cm<64, 32, false, 8, false><<<dim3(NB2, 2), 128>>>(
        C64b, 64, w_e1b, TAP2, NA2, LIST2, CNT + 2, C64c, 64, NV2);

    // d0u: 64 -> 32 (up to L1), write into CAT1 ch0..31
    up2cm<64, 16><<<dim3(NB1, 2), 128>>>(
        C64c, 64, w_d0u, LIST1, CNT + 1, CAT1, 64, G1);
    // d0a: 64 -> 64 relu (concat)
    conv3cm<64, 32, true, 8, false><<<dim3(NB1, 2), 128>>>(
        CAT1, 64, w_d0a, TAP1, NA1, LIST1, CNT + 1, B64, 64, NV1);
    // d0b: 64 -> 32
    conv3cm<64, 32, false, 8, false><<<dim3(NB1, 1), 128>>>(
        B64, 64, w_d0b, TAP1, NA1, LIST1, CNT + 1, B32a, 32, NV1);

    // d1u: 32 -> 16 (up to L0), write into CAT0 ch0..15
    up2cm<32, 16><<<dim3(NB0, 1), 128>>>(
        B32a, 32, w_d1u, LIST0, CNT + 0, CAT0, 32, G0);
    // d1a: 32 -> 32 relu (concat)
    conv3cm<32, 32, true, 8, false><<<dim3(NB0, 1), 128>>>(
        CAT0, 32, w_d1a, TAP0, NA0, LIST0, CNT + 0, A32, 32, NV0);
    // d1b: 32 -> 16
    conv3cm<32, 16, false, 8, false><<<dim3(NB0, 1), 128>>>(
        A32, 32, w_d1b, TAP0, NA0, LIST0, CNT + 0, A16a, 16, NV0);

    // out_a: 16 -> 16 relu
    conv3cm<16, 16, true, 8, false><<<dim3(NB0, 1), 128>>>(
        A16a, 16, w_oa, TAP0, NA0, LIST0, CNT + 0, A16b, 16, NV0);
    // out_b: 16 -> 5, planar output
    cudaMemsetAsync(d_out, 0, (size_t)out_size * sizeof(float));
    conv3cm<16, 5, false, 8, true><<<dim3(NB0, 1), 128>>>(
        A16b, 16, w_ob, TAP0, NA0, LIST0, CNT + 0, OUT, NV0, NV0);
}

// round 5
// speedup vs baseline: 2.2718x; 1.5530x over previous
#include <cuda_runtime.h>
#include <cstdint>

// ---------------------------------------------------------------------------
// Sparse (occupancy-masked) 3D U-Net, 96^3, NF=16.
// R4: tap-segmented gather-GEMM convs — per (block,tap) entry lists, smem
// accumulators, broadcast weight reads. Weight crossbar cost drops 4x.
// ---------------------------------------------------------------------------

#define G0 96
#define G1 48
#define G2 24
#define NV0 (G0*G0*G0)   // 884736
#define NV1 (G1*G1*G1)   // 110592
#define NV2 (G2*G2*G2)   // 13824
#define CB0 (NV0/256)
#define CB1 (NV1/256)
#define CB2 (NV2/256)
#define NB0 ((NV0+127)/128)  // 6912
#define NB1 ((NV1+127)/128)  // 864
#define NB2 ((NV2+127)/128)  // 108
#define ENTCAP 3456          // 128*27 entries per block

// Activations, channel-major [voxel][channel]
__device__ float g_XM  [NV0];
__device__ float g_CAT0[(size_t)32*NV0];
__device__ float g_A32 [(size_t)32*NV0];
__device__ float g_A16a[(size_t)16*NV0];
__device__ float g_A16b[(size_t)16*NV0];
__device__ float g_B32a[(size_t)32*NV1];
__device__ float g_B32b[(size_t)32*NV1];
__device__ float g_CAT1[(size_t)64*NV1];
__device__ float g_B64 [(size_t)64*NV1];
__device__ float g_C64a[(size_t)64*NV2];
__device__ float g_C64b[(size_t)64*NV2];
__device__ float g_C64c[(size_t)64*NV2];
__device__ float g_M1[NV1];
__device__ float g_M2[NV2];
__device__ float g_WT[64*64*27];           // transposed weights [tap][ci][co]

__device__ int g_LIST0[NV0], g_LIST1[NV1], g_LIST2[NV2];
__device__ int g_NA0[NV0];
__device__ int g_TAP0[(size_t)27*NV0];
__device__ int g_ENT0[(size_t)NB0*ENTCAP];
__device__ int g_ENT1[(size_t)NB1*ENTCAP];
__device__ int g_ENT2[(size_t)NB2*ENTCAP];
__device__ int g_SEG0[NB0*28], g_SEG1[NB1*28], g_SEG2[NB2*28];
__device__ int g_SGW0[NB0*27], g_SGW1[NB1*27], g_SGW2[NB2*27];
__device__ int g_SEGC[NB0*27];
__device__ int g_CNT[4];
__device__ int g_BCNT[CB0], g_BOFF[CB0];

// ---------------------------------------------------------------------------
__global__ void k_mask_input(const float* __restrict__ x,
                             const float* __restrict__ occ,
                             float* __restrict__ xm, int n)
{
    int v = blockIdx.x * blockDim.x + threadIdx.x;
    if (v < n) xm[v] = x[v] * occ[v];
}

__global__ void k_maxpool(const float* __restrict__ in,
                          float* __restrict__ out, int gout)
{
    int v = blockIdx.x * blockDim.x + threadIdx.x;
    int n = gout * gout * gout;
    if (v >= n) return;
    int gin = gout * 2;
    int z = v / (gout * gout), y = (v / gout) % gout, x = v % gout;
    float mx = 0.f;
    #pragma unroll
    for (int a = 0; a < 2; a++)
        #pragma unroll
        for (int b = 0; b < 2; b++)
            #pragma unroll
            for (int c = 0; c < 2; c++)
                mx = fmaxf(mx, in[((size_t)(2*z+a)*gin + (2*y+b))*gin + (2*x+c)]);
    out[v] = mx;
}

// --- deterministic compaction ---------------------------------------------
__global__ void k_count(const float* __restrict__ m, int n, int* __restrict__ bcnt)
{
    int v = blockIdx.x * 256 + threadIdx.x;
    bool a = (v < n) && (m[v] != 0.f);
    unsigned bal = __ballot_sync(0xffffffffu, a);
    __shared__ int wc[8];
    if ((threadIdx.x & 31) == 0) wc[threadIdx.x >> 5] = __popc(bal);
    __syncthreads();
    if (threadIdx.x == 0) {
        int s = 0;
        #pragma unroll
        for (int i = 0; i < 8; i++) s += wc[i];
        bcnt[blockIdx.x] = s;
    }
}

__global__ void k_scan(const int* __restrict__ bcnt, int nb,
                       int* __restrict__ boff, int* __restrict__ total)
{
    __shared__ int sh[1024];
    __shared__ int carry;
    if (threadIdx.x == 0) carry = 0;
    __syncthreads();
    for (int base = 0; base < nb; base += 1024) {
        int i = base + threadIdx.x;
        int v = (i < nb) ? bcnt[i] : 0;
        sh[threadIdx.x] = v;
        __syncthreads();
        for (int d = 1; d < 1024; d <<= 1) {
            int t = (threadIdx.x >= d) ? sh[threadIdx.x - d] : 0;
            __syncthreads();
            sh[threadIdx.x] += t;
            __syncthreads();
        }
        if (i < nb) boff[i] = carry + sh[threadIdx.x] - v;
        __syncthreads();
        if (threadIdx.x == 0) carry += sh[1023];
        __syncthreads();
    }
    if (threadIdx.x == 0) *total = carry;
}

__global__ void k_emit(const float* __restrict__ m, int n,
                       const int* __restrict__ boff, int* __restrict__ list)
{
    int v = blockIdx.x * 256 + threadIdx.x;
    bool a = (v < n) && (m[v] != 0.f);
    unsigned bal = __ballot_sync(0xffffffffu, a);
    __shared__ int wc[8];
    if ((threadIdx.x & 31) == 0) wc[threadIdx.x >> 5] = __popc(bal);
    __syncthreads();
    int wid = threadIdx.x >> 5;
    int off = boff[blockIdx.x];
    for (int i = 0; i < wid; i++) off += wc[i];
    off += __popc(bal & ((1u << (threadIdx.x & 31)) - 1u));
    if (a) list[off] = v;
}

// --- per-voxel tap lists (only used by the small CIN==1 / planar layers) --
__global__ void k_taps(const float* __restrict__ m, const int* __restrict__ list,
                       const int* __restrict__ cntp, int g, int cap,
                       int* __restrict__ TAP, int* __restrict__ NA)
{
    int cnt = *cntp;
    int t = blockIdx.x * 128 + threadIdx.x;
    if (t >= cnt) return;
    int v = list[t];
    int gg = g * g;
    int z = v / gg, y = (v / g) % g, x = v % g;
    int na = 0;
    #pragma unroll
    for (int dz = -1; dz <= 1; dz++) {
        int zz = z + dz; if ((unsigned)zz >= (unsigned)g) continue;
        #pragma unroll
        for (int dy = -1; dy <= 1; dy++) {
            int yy = y + dy; if ((unsigned)yy >= (unsigned)g) continue;
            int ro = (zz * g + yy) * g;
            #pragma unroll
            for (int dx = -1; dx <= 1; dx++) {
                int xx = x + dx; if ((unsigned)xx >= (unsigned)g) continue;
                int o = ro + xx;
                if (__ldg(m + o) != 0.f) {
                    int tap = (dz + 1) * 9 + (dy + 1) * 3 + (dx + 1);
                    TAP[(size_t)na * cap + t] = (tap << 24) | o;
                    na++;
                }
            }
        }
    }
    NA[t] = na;
}

// --- per-(block,tap) entry lists ------------------------------------------
__global__ void k_zeron(int* __restrict__ a, int n)
{
    int i = blockIdx.x * 256 + threadIdx.x;
    if (i < n) a[i] = 0;
}

__global__ void k_entcnt(const float* __restrict__ m, const int* __restrict__ list,
                         const int* __restrict__ cntp, int g, int* __restrict__ segc)
{
    int cnt = *cntp;
    int t = blockIdx.x * 128 + threadIdx.x;
    if (t >= cnt) return;
    int v = list[t];
    int b = t >> 7;
    int gg = g * g;
    int z = v / gg, y = (v / g) % g, x = v % g;
    #pragma unroll
    for (int dz = -1; dz <= 1; dz++) {
        int zz = z + dz; if ((unsigned)zz >= (unsigned)g) continue;
        #pragma unroll
        for (int dy = -1; dy <= 1; dy++) {
            int yy = y + dy; if ((unsigned)yy >= (unsigned)g) continue;
            int ro = (zz * g + yy) * g;
            #pragma unroll
            for (int dx = -1; dx <= 1; dx++) {
                int xx = x + dx; if ((unsigned)xx >= (unsigned)g) continue;
                if (__ldg(m + ro + xx) != 0.f) {
                    int tap = (dz + 1) * 9 + (dy + 1) * 3 + (dx + 1);
                    atomicAdd(&segc[b * 27 + tap], 1);
                }
            }
        }
    }
}

__global__ void k_segscan(const int* __restrict__ segc, int nb,
                          int* __restrict__ seg, int* __restrict__ segw)
{
    int b = blockIdx.x * 256 + threadIdx.x;
    if (b >= nb) return;
    int s = 0;
    #pragma unroll
    for (int t = 0; t < 27; t++) {
        seg[b * 28 + t] = s;
        segw[b * 27 + t] = s;
        s += segc[b * 27 + t];
    }
    seg[b * 28 + 27] = s;
}

__global__ void k_entscatter(const float* __restrict__ m, const int* __restrict__ list,
                             const int* __restrict__ cntp, int g,
                             int* __restrict__ segw, int* __restrict__ ENT)
{
    int cnt = *cntp;
    int t = blockIdx.x * 128 + threadIdx.x;
    if (t >= cnt) return;
    int v = list[t];
    int b = t >> 7;
    int slot = t & 127;
    int gg = g * g;
    int z = v / gg, y = (v / g) % g, x = v % g;
    #pragma unroll
    for (int dz = -1; dz <= 1; dz++) {
        int zz = z + dz; if ((unsigned)zz >= (unsigned)g) continue;
        #pragma unroll
        for (int dy = -1; dy <= 1; dy++) {
            int yy = y + dy; if ((unsigned)yy >= (unsigned)g) continue;
            int ro = (zz * g + yy) * g;
            #pragma unroll
            for (int dx = -1; dx <= 1; dx++) {
                int xx = x + dx; if ((unsigned)xx >= (unsigned)g) continue;
                int o = ro + xx;
                if (__ldg(m + o) != 0.f) {
                    int tap = (dz + 1) * 9 + (dy + 1) * 3 + (dx + 1);
                    int pos = atomicAdd(&segw[b * 27 + tap], 1);
                    ENT[(size_t)b * ENTCAP + pos] = (slot << 24) | o;
                }
            }
        }
    }
}

// --- weight transpose: OIDHW -> [tap][ci][co] ------------------------------
__global__ void k_wtrans(const float* __restrict__ w, int cin, int cout,
                         float* __restrict__ wt)
{
    int i = blockIdx.x * 256 + threadIdx.x;
    int tot = cout * cin * 27;
    if (i >= tot) return;
    int co = i % cout;
    int r = i / cout;
    int ci = r % cin;
    int tap = r / cin;
    wt[i] = w[((size_t)co * cin + ci) * 27 + tap];
}

// ---------------------------------------------------------------------------
// Tap-segmented gather-GEMM conv. All lanes process the same tap at once:
// weight reads are warp-broadcast (16B/4FFMA crossbar). Accumulation in
// padded smem, deterministic (ascending tap order; one entry per voxel/tap).
// ---------------------------------------------------------------------------
template<int CIN, int COB, bool RELU>
__launch_bounds__(128)
__global__ void convgemm(const float* __restrict__ in, int istr,
                         const float* __restrict__ wt, int couttot,
                         const int* __restrict__ ENT, const int* __restrict__ SEG,
                         const int* __restrict__ list, const int* __restrict__ cntp,
                         float* __restrict__ out, int ostr)
{
    constexpr int ASTR = COB + 1;   // coprime-with-32 stride: conflict-free
    constexpr int WSTR = COB + 4;   // 16B-aligned rows for float4 broadcast
    __shared__ float acc[128 * ASTR];
    __shared__ float wsh[CIN * WSTR];
    const int cnt = *cntp;
    const int b = blockIdx.x;
    if (b * 128 >= cnt) return;
    const int co0 = blockIdx.y * COB;
    const int tid = threadIdx.x;

    for (int i = tid; i < 128 * ASTR; i += 128) acc[i] = 0.f;

    for (int tap = 0; tap < 27; tap++) {
        __syncthreads();
        for (int i = tid; i < CIN * COB; i += 128) {
            int ci = i / COB, co = i - ci * COB;
            wsh[ci * WSTR + co] = __ldg(wt + (size_t)(tap * CIN + ci) * couttot + co0 + co);
        }
        __syncthreads();
        const int s = SEG[b * 28 + tap];
        const int n = SEG[b * 28 + tap + 1] - s;
        if (tid < n) {
            int ent = ENT[(size_t)b * ENTCAP + s + tid];
            int slot = ent >> 24;
            int vin  = ent & 0xFFFFFF;
            const float* xr = in + (size_t)vin * istr;
            float a[COB];
            #pragma unroll
            for (int co = 0; co < COB; co++) a[co] = 0.f;
            #pragma unroll 1
            for (int ci0 = 0; ci0 < CIN; ci0 += 8) {
                float4 x0 = *reinterpret_cast<const float4*>(xr + ci0);
                float4 x1 = *reinterpret_cast<const float4*>(xr + ci0 + 4);
                float xs[8] = {x0.x, x0.y, x0.z, x0.w, x1.x, x1.y, x1.z, x1.w};
                #pragma unroll
                for (int j = 0; j < 8; j++) {
                    const float* wr = &wsh[(ci0 + j) * WSTR];
                    #pragma unroll
                    for (int co4 = 0; co4 < COB; co4 += 4) {
                        float4 w = *reinterpret_cast<const float4*>(wr + co4);
                        a[co4+0] += xs[j] * w.x;
                        a[co4+1] += xs[j] * w.y;
                        a[co4+2] += xs[j] * w.z;
                        a[co4+3] += xs[j] * w.w;
                    }
                }
            }
            float* ap = &acc[slot * ASTR];
            #pragma unroll
            for (int co = 0; co < COB; co++) ap[co] += a[co];
        }
    }
    __syncthreads();
    const int t = b * 128 + tid;
    if (t < cnt) {
        int v = list[t];
        float* op = out + (size_t)v * ostr + co0;
        const float* ap = &acc[tid * ASTR];
        #pragma unroll
        for (int co = 0; co < COB; co += 4) {
            float4 r = make_float4(ap[co], ap[co+1], ap[co+2], ap[co+3]);
            if (RELU) { r.x = fmaxf(r.x, 0.f); r.y = fmaxf(r.y, 0.f);
                        r.z = fmaxf(r.z, 0.f); r.w = fmaxf(r.w, 0.f); }
            *reinterpret_cast<float4*>(op + co) = r;
        }
    }
}

// ---------------------------------------------------------------------------
// R3-style conv kept for CIN==1 (conv_in) and planar-out (out_b) layers.
// ---------------------------------------------------------------------------
template<int CIN, int COB, bool RELU, int CHUNK, bool OUTP>
__launch_bounds__(128)
__global__ void conv3cm(const float* __restrict__ in, int istr,
                        const float* __restrict__ wgl,
                        const int* __restrict__ TAP, const int* __restrict__ NAs,
                        const int* __restrict__ list, const int* __restrict__ cntp,
                        float* __restrict__ out, int ostr, int cap)
{
    constexpr int WPAD = COB + 1;
    __shared__ float wsh[CHUNK * 27 * WPAD];
    const int cnt = *cntp;
    if (blockIdx.x * 128 >= cnt) return;
    const int co0 = blockIdx.y * COB;
    const int t   = blockIdx.x * 128 + threadIdx.x;
    const bool act = t < cnt;
    const int v  = act ? list[t] : 0;
    const int na = act ? NAs[t] : 0;

    float acc[COB];
    #pragma unroll
    for (int co = 0; co < COB; co++) acc[co] = 0.f;

    for (int ci0 = 0; ci0 < CIN; ci0 += CHUNK) {
        __syncthreads();
        for (int i = threadIdx.x; i < CHUNK * 27 * COB; i += 128) {
            int cil = i / (27 * COB);
            int rem = i - cil * (27 * COB);
            int tap = rem / COB;
            int co  = rem - tap * COB;
            wsh[(cil * 27 + tap) * WPAD + co] =
                wgl[((size_t)(co0 + co) * CIN + (ci0 + cil)) * 27 + tap];
        }
        __syncthreads();

        if constexpr (CIN == 1) {
            for (int k = 0; k < na; k++) {
                int p = __ldg(TAP + (size_t)k * cap + t);
                float xs = __ldg(in + (p & 0xFFFFFF));
                const float* wr = &wsh[(p >> 24) * WPAD];
                #pragma unroll
                for (int co = 0; co < COB; co++) acc[co] += xs * wr[co];
            }
        } else {
            for (int k = 0; k < na; k++) {
                int p = __ldg(TAP + (size_t)k * cap + t);
                int off = p & 0xFFFFFF;
                int tap = p >> 24;
                const float* xin = in + (size_t)off * istr + ci0;
                #pragma unroll
                for (int cq = 0; cq < CHUNK / 4; cq++) {
                    float4 xv = *reinterpret_cast<const float4*>(xin + cq * 4);
                    #pragma unroll
                    for (int j = 0; j < 4; j++) {
                        float xsv = (j == 0) ? xv.x : (j == 1) ? xv.y : (j == 2) ? xv.z : xv.w;
                        const float* wr = &wsh[((cq * 4 + j) * 27 + tap) * WPAD];
                        #pragma unroll
                        for (int co = 0; co < COB; co++) acc[co] += xsv * wr[co];
                    }
                }
            }
        }
    }

    if (act) {
        if constexpr (OUTP) {
            #pragma unroll
            for (int co = 0; co < COB; co++) {
                float r = acc[co];
                if (RELU) r = fmaxf(r, 0.f);
                out[(size_t)(co0 + co) * ostr + v] = r;
            }
        } else {
            float* op = out + (size_t)v * ostr + co0;
            #pragma unroll
            for (int co = 0; co < COB; co += 4) {
                float4 r = make_float4(acc[co], acc[co+1], acc[co+2], acc[co+3]);
                if (RELU) { r.x = fmaxf(r.x, 0.f); r.y = fmaxf(r.y, 0.f);
                            r.z = fmaxf(r.z, 0.f); r.w = fmaxf(r.w, 0.f); }
                *reinterpret_cast<float4*>(op + co) = r;
            }
        }
    }
}

// ---------------------------------------------------------------------------
// Stride-2 k=2 downsample / k=2 s=2 transpose upsample (unchanged from R3).
// ---------------------------------------------------------------------------
template<int CIN, int COB>
__launch_bounds__(128)
__global__ void down2cm(const float* __restrict__ in, int istr,
                        const float* __restrict__ wgl,
                        const float* __restrict__ maskf,
                        const int* __restrict__ list, const int* __restrict__ cntp,
                        float* __restrict__ out, int ostr, int gout)
{
    constexpr int WPAD = COB + 1;
    __shared__ float wsh[CIN * 8 * WPAD];
    const int cnt = *cntp;
    if (blockIdx.x * 128 >= cnt) return;
    const int co0 = blockIdx.y * COB;
    for (int i = threadIdx.x; i < CIN * 8 * COB; i += 128) {
        int ci  = i / (8 * COB);
        int rem = i - ci * (8 * COB);
        int tap = rem / COB;
        int co  = rem - tap * COB;
        wsh[(ci * 8 + tap) * WPAD + co] = wgl[((size_t)(co0 + co) * CIN + ci) * 8 + tap];
    }
    __syncthreads();

    const int t = blockIdx.x * 128 + threadIdx.x;
    const bool act = t < cnt;
    const int v = act ? list[t] : 0;
    const int z = v / (gout * gout), y = (v / gout) % gout, x = v % gout;
    const int gin = gout * 2;

    float acc[COB];
    #pragma unroll
    for (int co = 0; co < COB; co++) acc[co] = 0.f;

    #pragma unroll
    for (int tap = 0; tap < 8; tap++) {
        int kd = tap >> 2, kh = (tap >> 1) & 1, kw = tap & 1;
        int off = ((2*z + kd) * gin + (2*y + kh)) * gin + (2*x + kw);
        if (act && __ldg(maskf + off) != 0.f) {
            const float* xin = in + (size_t)off * istr;
            #pragma unroll
            for (int cq = 0; cq < CIN / 4; cq++) {
                float4 xv = *reinterpret_cast<const float4*>(xin + cq * 4);
                #pragma unroll
                for (int j = 0; j < 4; j++) {
                    float xs = (j == 0) ? xv.x : (j == 1) ? xv.y : (j == 2) ? xv.z : xv.w;
                    const float* wr = &wsh[((cq * 4 + j) * 8 + tap) * WPAD];
                    #pragma unroll
                    for (int co = 0; co < COB; co++) acc[co] += xs * wr[co];
                }
            }
        }
    }

    if (act) {
        float* op = out + (size_t)v * ostr + co0;
        #pragma unroll
        for (int co = 0; co < COB; co += 4)
            *reinterpret_cast<float4*>(op + co) =
                make_float4(acc[co], acc[co+1], acc[co+2], acc[co+3]);
    }
}

template<int CIN, int COB>
__launch_bounds__(128)
__global__ void up2cm(const float* __restrict__ in, int istr,
                      const float* __restrict__ wgl,
                      const int* __restrict__ list, const int* __restrict__ cntp,
                      float* __restrict__ out, int ostr, int gout)
{
    constexpr int WPAD = COB + 1;
    __shared__ float wsh[CIN * 8 * WPAD];
    const int cnt = *cntp;
    if (blockIdx.x * 128 >= cnt) return;
    const int co0 = blockIdx.y * COB;
    for (int i = threadIdx.x; i < CIN * 8 * COB; i += 128) {
        int ci  = i / (8 * COB);
        int rem = i - ci * (8 * COB);
        int tap = rem / COB;
        int co  = rem - tap * COB;
        wsh[(ci * 8 + tap) * WPAD + co] = wgl[((size_t)(co0 + co) * CIN + ci) * 8 + tap];
    }
    __syncthreads();

    const int t = blockIdx.x * 128 + threadIdx.x;
    const bool act = t < cnt;
    const int v = act ? list[t] : 0;
    const int z = v / (gout * gout), y = (v / gout) % gout, x = v % gout;
    const int gin = gout >> 1;
    const int p   = ((z >> 1) * gin + (y >> 1)) * gin + (x >> 1);
    const int tap = (1 - (z & 1)) * 4 + (1 - (y & 1)) * 2 + (1 - (x & 1));

    float acc[COB];
    #pragma unroll
    for (int co = 0; co < COB; co++) acc[co] = 0.f;

    if (act) {
        const float* xin = in + (size_t)p * istr;
        #pragma unroll
        for (int cq = 0; cq < CIN / 4; cq++) {
            float4 xv = *reinterpret_cast<const float4*>(xin + cq * 4);
            #pragma unroll
            for (int j = 0; j < 4; j++) {
                float xs = (j == 0) ? xv.x : (j == 1) ? xv.y : (j == 2) ? xv.z : xv.w;
                const float* wr = &wsh[((cq * 4 + j) * 8 + tap) * WPAD];
                #pragma unroll
                for (int co = 0; co < COB; co++) acc[co] += xs * wr[co];
            }
        }
        float* op = out + (size_t)v * ostr + co0;
        #pragma unroll
        for (int co = 0; co < COB; co += 4)
            *reinterpret_cast<float4*>(op + co) =
                make_float4(acc[co], acc[co+1], acc[co+2], acc[co+3]);
    }
}

// ---------------------------------------------------------------------------
extern "C" void kernel_launch(void* const* d_in, const int* in_sizes, int n_in,
                              void* d_out, int out_size)
{
    const float* x     = (const float*)d_in[0];
    const float* occ   = (const float*)d_in[1];
    const float* w_in  = (const float*)d_in[2];
    const float* w_e0d = (const float*)d_in[3];
    const float* w_e0a = (const float*)d_in[4];
    const float* w_e0b = (const float*)d_in[5];
    const float* w_e1d = (const float*)d_in[6];
    const float* w_e1a = (const float*)d_in[7];
    const float* w_e1b = (const float*)d_in[8];
    const float* w_d0u = (const float*)d_in[9];
    const float* w_d0a = (const float*)d_in[10];
    const float* w_d0b = (const float*)d_in[11];
    const float* w_d1u = (const float*)d_in[12];
    const float* w_d1a = (const float*)d_in[13];
    const float* w_d1b = (const float*)d_in[14];
    const float* w_oa  = (const float*)d_in[15];
    const float* w_ob  = (const float*)d_in[16];

    float *XM, *CAT0, *A32, *A16a, *A16b, *B32a, *B32b, *CAT1, *B64;
    float *C64a, *C64b, *C64c, *M1, *M2, *WT;
    int *LIST0, *LIST1, *LIST2, *NA0, *TAP0;
    int *ENT0, *ENT1, *ENT2, *SEG0, *SEG1, *SEG2, *SGW0, *SGW1, *SGW2, *SEGC;
    int *CNT, *BCNT, *BOFF;
    cudaGetSymbolAddress((void**)&XM,   g_XM);
    cudaGetSymbolAddress((void**)&CAT0, g_CAT0);
    cudaGetSymbolAddress((void**)&A32,  g_A32);
    cudaGetSymbolAddress((void**)&A16a, g_A16a);
    cudaGetSymbolAddress((void**)&A16b, g_A16b);
    cudaGetSymbolAddress((void**)&B32a, g_B32a);
    cudaGetSymbolAddress((void**)&B32b, g_B32b);
    cudaGetSymbolAddress((void**)&CAT1, g_CAT1);
    cudaGetSymbolAddress((void**)&B64,  g_B64);
    cudaGetSymbolAddress((void**)&C64a, g_C64a);
    cudaGetSymbolAddress((void**)&C64b, g_C64b);
    cudaGetSymbolAddress((void**)&C64c, g_C64c);
    cudaGetSymbolAddress((void**)&M1,   g_M1);
    cudaGetSymbolAddress((void**)&M2,   g_M2);
    cudaGetSymbolAddress((void**)&WT,   g_WT);
    cudaGetSymbolAddress((void**)&LIST0, g_LIST0);
    cudaGetSymbolAddress((void**)&LIST1, g_LIST1);
    cudaGetSymbolAddress((void**)&LIST2, g_LIST2);
    cudaGetSymbolAddress((void**)&NA0,   g_NA0);
    cudaGetSymbolAddress((void**)&TAP0,  g_TAP0);
    cudaGetSymbolAddress((void**)&ENT0,  g_ENT0);
    cudaGetSymbolAddress((void**)&ENT1,  g_ENT1);
    cudaGetSymbolAddress((void**)&ENT2,  g_ENT2);
    cudaGetSymbolAddress((void**)&SEG0,  g_SEG0);
    cudaGetSymbolAddress((void**)&SEG1,  g_SEG1);
    cudaGetSymbolAddress((void**)&SEG2,  g_SEG2);
    cudaGetSymbolAddress((void**)&SGW0,  g_SGW0);
    cudaGetSymbolAddress((void**)&SGW1,  g_SGW1);
    cudaGetSymbolAddress((void**)&SGW2,  g_SGW2);
    cudaGetSymbolAddress((void**)&SEGC,  g_SEGC);
    cudaGetSymbolAddress((void**)&CNT,   g_CNT);
    cudaGetSymbolAddress((void**)&BCNT,  g_BCNT);
    cudaGetSymbolAddress((void**)&BOFF,  g_BOFF);

    float* OUT = (float*)d_out;

    // Masks + masked input
    k_mask_input<<<NV0/128, 128>>>(x, occ, XM, NV0);
    k_maxpool<<<NB1, 128>>>(occ, M1, G1);
    k_maxpool<<<NB2, 128>>>(M1, M2, G2);

    // Level 0: compact + per-voxel taps (for conv_in/out_b) + block-tap entries
    k_count<<<CB0, 256>>>(occ, NV0, BCNT);
    k_scan <<<1, 1024>>>(BCNT, CB0, BOFF, CNT + 0);
    k_emit <<<CB0, 256>>>(occ, NV0, BOFF, LIST0);
    k_taps<<<NB0, 128>>>(occ, LIST0, CNT + 0, G0, NV0, TAP0, NA0);
    k_zeron<<<(NB0*27+255)/256, 256>>>(SEGC, NB0*27);
    k_entcnt<<<NB0, 128>>>(occ, LIST0, CNT + 0, G0, SEGC);
    k_segscan<<<(NB0+255)/256, 256>>>(SEGC, NB0, SEG0, SGW0);
    k_entscatter<<<NB0, 128>>>(occ, LIST0, CNT + 0, G0, SGW0, ENT0);

    // Level 1
    k_count<<<CB1, 256>>>(M1, NV1, BCNT);
    k_scan <<<1, 1024>>>(BCNT, CB1, BOFF, CNT + 1);
    k_emit <<<CB1, 256>>>(M1, NV1, BOFF, LIST1);
    k_zeron<<<(NB1*27+255)/256, 256>>>(SEGC, NB1*27);
    k_entcnt<<<NB1, 128>>>(M1, LIST1, CNT + 1, G1, SEGC);
    k_segscan<<<(NB1+255)/256, 256>>>(SEGC, NB1, SEG1, SGW1);
    k_entscatter<<<NB1, 128>>>(M1, LIST1, CNT + 1, G1, SGW1, ENT1);

    // Level 2
    k_count<<<CB2, 256>>>(M2, NV2, BCNT);
    k_scan <<<1, 1024>>>(BCNT, CB2, BOFF, CNT + 2);
    k_emit <<<CB2, 256>>>(M2, NV2, BOFF, LIST2);
    k_zeron<<<(NB2*27+255)/256, 256>>>(SEGC, NB2*27);
    k_entcnt<<<NB2, 128>>>(M2, LIST2, CNT + 2, G2, SEGC);
    k_segscan<<<(NB2+255)/256, 256>>>(SEGC, NB2, SEG2, SGW2);
    k_entscatter<<<NB2, 128>>>(M2, LIST2, CNT + 2, G2, SGW2, ENT2);

    // ---- network ----
    // conv_in: 1 -> 16 (skip0 -> CAT0 ch16..31)
    conv3cm<1, 16, false, 1, false><<<dim3(NB0, 1), 128>>>(
        XM, 1, w_in, TAP0, NA0, LIST0, CNT + 0, CAT0 + 16, 32, NV0);

    // e0d: 16 -> 32
    down2cm<16, 32><<<dim3(NB1, 1), 128>>>(
        CAT0 + 16, 32, w_e0d, occ, LIST1, CNT + 1, B32a, 32, G1);
    // e0a: 32 -> 32 relu
    k_wtrans<<<(32*32*27+255)/256, 256>>>(w_e0a, 32, 32, WT);
    convgemm<32, 32, true><<<dim3(NB1, 1), 128>>>(
        B32a, 32, WT, 32, ENT1, SEG1, LIST1, CNT + 1, B32b, 32);
    // e0b: 32 -> 32 (skip1 -> CAT1 ch32..63)
    k_wtrans<<<(32*32*27+255)/256, 256>>>(w_e0b, 32, 32, WT);
    convgemm<32, 32, false><<<dim3(NB1, 1), 128>>>(
        B32b, 32, WT, 32, ENT1, SEG1, LIST1, CNT + 1, CAT1 + 32, 64);

    // e1d: 32 -> 64
    down2cm<32, 32><<<dim3(NB2, 2), 128>>>(
        CAT1 + 32, 64, w_e1d, M1, LIST2, CNT + 2, C64a, 64, G2);
    // e1a: 64 -> 64 relu
    k_wtrans<<<(64*64*27+255)/256, 256>>>(w_e1a, 64, 64, WT);
    convgemm<64, 32, true><<<dim3(NB2, 2), 128>>>(
        C64a, 64, WT, 64, ENT2, SEG2, LIST2, CNT + 2, C64b, 64);
    // e1b: 64 -> 64
    k_wtrans<<<(64*64*27+255)/256, 256>>>(w_e1b, 64, 64, WT);
    convgemm<64, 32, false><<<dim3(NB2, 2), 128>>>(
        C64b, 64, WT, 64, ENT2, SEG2, LIST2, CNT + 2, C64c, 64);

    // d0u: 64 -> 32 (into CAT1 ch0..31)
    up2cm<64, 16><<<dim3(NB1, 2), 128>>>(
        C64c, 64, w_d0u, LIST1, CNT + 1, CAT1, 64, G1);
    // d0a: 64 -> 64 relu (concat)
    k_wtrans<<<(64*64*27+255)/256, 256>>>(w_d0a, 64, 64, WT);
    convgemm<64, 32, true><<<dim3(NB1, 2), 128>>>(
        CAT1, 64, WT, 64, ENT1, SEG1, LIST1, CNT + 1, B64, 64);
    // d0b: 64 -> 32
    k_wtrans<<<(64*32*27+255)/256, 256>>>(w_d0b, 64, 32, WT);
    convgemm<64, 32, false><<<dim3(NB1, 1), 128>>>(
        B64, 64, WT, 32, ENT1, SEG1, LIST1, CNT + 1, B32a, 32);

    // d1u: 32 -> 16 (into CAT0 ch0..15)
    up2cm<32, 16><<<dim3(NB0, 1), 128>>>(
        B32a, 32, w_d1u, LIST0, CNT + 0, CAT0, 32, G0);
    // d1a: 32 -> 32 relu (concat)
    k_wtrans<<<(32*32*27+255)/256, 256>>>(w_d1a, 32, 32, WT);
    convgemm<32, 32, true><<<dim3(NB0, 1), 128>>>(
        CAT0, 32, WT, 32, ENT0, SEG0, LIST0, CNT + 0, A32, 32);
    // d1b: 32 -> 16
    k_wtrans<<<(32*16*27+255)/256, 256>>>(w_d1b, 32, 16, WT);
    convgemm<32, 16, false><<<dim3(NB0, 1), 128>>>(
        A32, 32, WT, 16, ENT0, SEG0, LIST0, CNT + 0, A16a, 16);

    // out_a: 16 -> 16 relu
    k_wtrans<<<(16*16*27+255)/256, 256>>>(w_oa, 16, 16, WT);
    convgemm<16, 16, true><<<dim3(NB0, 1), 128>>>(
        A16a, 16, WT, 16, ENT0, SEG0, LIST0, CNT + 0, A16b, 16);

    // out_b: 16 -> 5, planar output
    cudaMemsetAsync(d_out, 0, (size_t)out_size * sizeof(float));
    conv3cm<16, 5, false, 8, true><<<dim3(NB0, 1), 128>>>(
        A16b, 16, w_ob, TAP0, NA0, LIST0, CNT + 0, OUT, NV0, NV0);
}